// round 15
// baseline (speedup 1.0000x reference)
#include <cuda_runtime.h>
#include <cuda_fp16.h>
#include <cstdint>

// Problem constants
#define MM 8192
#define NN 8192
#define KK 4096
#define TM 128
#define TN 256
#define KS 128              // K elems per pipeline stage (256B rows)
#define STAGES 2
#define K_ITERS (KK / KS)   // 32 (even)

// Static scratch (allocation-free rule: __device__ globals): 64 MB + 64 MB
__device__ __half g_Ah[(size_t)MM * KK];
__device__ __half g_Wh[(size_t)NN * KK];

// ---------------------------------------------------------------------------
// Fused prep kernel (512 threads).
// ---------------------------------------------------------------------------
#define A_BLOCKS (MM * KK / 8 / 512)             // 8192
#define W_BLOCKS ((NN / 512) * ((KK / 8) / 8))   // 1024

__global__ void prep_kernel(const float* __restrict__ A, __half* __restrict__ Ah,
                            const int* __restrict__ Bp, const float* __restrict__ s,
                            __half* __restrict__ Wh) {
    int b = blockIdx.x;
    if (b < A_BLOCKS) {
        size_t base = ((size_t)b * 512 + threadIdx.x) * 8;
        float4 v0 = *reinterpret_cast<const float4*>(A + base);
        float4 v1 = *reinterpret_cast<const float4*>(A + base + 4);
        union { __half h[8]; uint4 u; } out;
        out.h[0] = __float2half(v0.x); out.h[1] = __float2half(v0.y);
        out.h[2] = __float2half(v0.z); out.h[3] = __float2half(v0.w);
        out.h[4] = __float2half(v1.x); out.h[5] = __float2half(v1.y);
        out.h[6] = __float2half(v1.z); out.h[7] = __float2half(v1.w);
        *reinterpret_cast<uint4*>(Ah + base) = out.u;
    } else {
        int bw  = b - A_BLOCKS;
        int n   = (bw & 15) * 512 + threadIdx.x;      // 16 x-blocks
        int kp0 = (bw >> 4) * 8;                      // 8 packed rows = 64 k
        float sv = s[(size_t)(kp0 >> 4) * NN + n];    // group = kp/16
        __half* dst = Wh + (size_t)n * KK + kp0 * 8;
#pragma unroll
        for (int r = 0; r < 8; r++) {
            int packed = Bp[(size_t)(kp0 + r) * NN + n];
            union { __half h[8]; uint4 u; } out;
#pragma unroll
            for (int j = 0; j < 8; j++) {
                int q = (packed >> (4 * j)) & 0xF;
                out.h[j] = __float2half((float)(q - 8) * sv);
            }
            *reinterpret_cast<uint4*>(dst + r * 8) = out.u;
        }
    }
}

// ---------------------------------------------------------------------------
// GEMM: C[M,N] = Ah @ Wh^T (fp16 in, f32 acc)
// CTA 128x256, 512 threads, 16 warps (2m x 8n), warp tile 64x32.
// 2-stage cp.async pipeline, KS=128; outer loop unrolled x2 (hard parity).
// MMA asm is NON-volatile: pure register dataflow, so ptxas may software-
// pipeline MMAs against the next kt's LDSMs. LDSM/cp.async stay volatile
// (they touch shared memory across the barrier).
// ---------------------------------------------------------------------------
#define A_STAGE_BYTES 32768              // 128 x 128 x 2
#define B_STAGE_BYTES 65536              // 256 x 128 x 2
#define B_REGION (STAGES * A_STAGE_BYTES)                       // 65536
#define SMEM_BYTES (STAGES * (A_STAGE_BYTES + B_STAGE_BYTES))   // 196608
#define ROWSTEP (32 * KK)                // halves: 32 rows of gmem
#define SROWSTEP 8192                    // bytes: 32 rows of smem stage

__device__ __forceinline__ uint32_t smem_u32(const void* p) {
    uint32_t a;
    asm("{ .reg .u64 t; cvta.to.shared.u64 t, %1; cvt.u32.u64 %0, t; }" : "=r"(a) : "l"(p));
    return a;
}

#define CP_ASYNC16(smem, gmem) \
    asm volatile("cp.async.cg.shared.global [%0], [%1], 16;" :: "r"(smem), "l"(gmem))
#define CP_COMMIT() asm volatile("cp.async.commit_group;" ::: "memory")
#define CP_WAIT0()  asm volatile("cp.async.wait_group 0;" ::: "memory")

#define LDSM_X4(r, addr) \
    asm volatile("ldmatrix.sync.aligned.m8n8.x4.shared.b16 {%0,%1,%2,%3}, [%4];" \
        : "=r"((r)[0]), "=r"((r)[1]), "=r"((r)[2]), "=r"((r)[3]) : "r"(addr))

// NON-volatile: pure register op; ordering enforced solely by data deps.
#define MMA16816(d, a, b0, b1) \
    asm("mma.sync.aligned.m16n8k16.row.col.f32.f16.f16.f32 " \
        "{%0,%1,%2,%3}, {%4,%5,%6,%7}, {%8,%9}, {%0,%1,%2,%3};" \
        : "+f"((d)[0]), "+f"((d)[1]), "+f"((d)[2]), "+f"((d)[3]) \
        : "r"((a)[0]), "r"((a)[1]), "r"((a)[2]), "r"((a)[3]), "r"(b0), "r"(b1))

__global__ __launch_bounds__(512, 1) void gemm_kernel(
    const __half* __restrict__ gA,
    const __half* __restrict__ gB,
    float* __restrict__ C)
{
    extern __shared__ char smem[];
    const uint32_t sbase = smem_u32(smem);
    const int tid = threadIdx.x, wid = tid >> 5, lid = tid & 31;

    // CTA swizzle: 8-wide m-bands sweeping n (L2 reuse)
    const int TILES_N = NN / TN;        // 32
    int bid  = blockIdx.x;
    int band = bid / (8 * TILES_N);
    int rem  = bid % (8 * TILES_N);
    const int m0 = (band * 8 + (rem % 8)) * TM;
    const int n0 = (rem / 8) * TN;

    const int warpM = (wid & 1) * 64;   // 2 m-warps
    const int warpN = (wid >> 1) * 32;  // 8 n-warps

    // cp.async mapping: base row = tid>>4 (0..31), chunk c = tid&15.
    const int vb = tid >> 4, cchk = tid & 15;
    const uint32_t soffBase = (uint32_t)vb * 256 + (uint32_t)((cchk ^ (vb & 7)) << 4);
    const __half* pAg = gA + (size_t)(m0 + vb) * KK + cchk * 8;
    const __half* pBg = gB + (size_t)(n0 + vb) * KK + cchk * 8;

    // Hoisted cp.async destination bases (per parity)
    const uint32_t wA0 = sbase + soffBase;
    const uint32_t wA1 = wA0 + A_STAGE_BYTES;
    const uint32_t wB0 = sbase + B_REGION + soffBase;
    const uint32_t wB1 = wB0 + B_STAGE_BYTES;

    // Prologue: fill stage 0
    {
#pragma unroll
        for (int r = 0; r < 4; r++) CP_ASYNC16(wA0 + r * SROWSTEP, pAg + (size_t)r * ROWSTEP);
#pragma unroll
        for (int r = 0; r < 8; r++) CP_ASYNC16(wB0 + r * SROWSTEP, pBg + (size_t)r * ROWSTEP);
        CP_COMMIT();
        pAg += KS; pBg += KS;
    }

    float acc[4][4][4];
#pragma unroll
    for (int mi = 0; mi < 4; mi++)
#pragma unroll
        for (int ni = 0; ni < 4; ni++)
#pragma unroll
            for (int v = 0; v < 4; v++) acc[mi][ni][v] = 0.f;

    const int lrow  = lid & 15;          // row within 16-row subtile
    const int lhalf = lid >> 4;          // k-chunk half (0/1)
    const int lsw   = lrow & 7;          // swizzle key

    // Hoisted LDSM read bases (per parity)
    const uint32_t rA0 = sbase + (uint32_t)(warpM + lrow) * 256;
    const uint32_t rA1 = rA0 + A_STAGE_BYTES;
    const uint32_t rB0 = sbase + B_REGION + (uint32_t)(warpN + lrow) * 256;
    const uint32_t rB1 = rB0 + B_STAGE_BYTES;

    // One stage body: read (aR,bR), load next stage into (lA,lB).
    auto body = [&](uint32_t aR, uint32_t bR, uint32_t lA, uint32_t lB, bool doLoad) {
        CP_WAIT0();
        __syncthreads();
#pragma unroll
        for (int kt = 0; kt < 8; kt++) {
            const uint32_t off = (uint32_t)(((kt * 2 + lhalf) ^ lsw) << 4);
            const uint32_t aAdr = aR + off;
            const uint32_t bAdr = bR + off;
            uint32_t fa[4][4], fb[2][4];
            LDSM_X4(fa[0], aAdr);
            LDSM_X4(fb[0], bAdr);
            LDSM_X4(fb[1], bAdr + 4096);
            LDSM_X4(fa[1], aAdr + 4096);
            LDSM_X4(fa[2], aAdr + 8192);
            LDSM_X4(fa[3], aAdr + 12288);
            // Next stage's cp.asyncs: 2 per slot, kt0..5
            if (doLoad && kt < 6) {
                if (kt < 4) {
                    CP_ASYNC16(lA + kt * SROWSTEP, pAg + (size_t)kt * ROWSTEP);
                    CP_ASYNC16(lB + kt * SROWSTEP, pBg + (size_t)kt * ROWSTEP);
                } else {
                    CP_ASYNC16(lB + (2 * kt - 4) * SROWSTEP, pBg + (size_t)(2 * kt - 4) * ROWSTEP);
                    CP_ASYNC16(lB + (2 * kt - 3) * SROWSTEP, pBg + (size_t)(2 * kt - 3) * ROWSTEP);
                }
            }
            if (kt == 5) { CP_COMMIT(); }
#pragma unroll
            for (int mi = 0; mi < 4; mi++)
#pragma unroll
                for (int ni = 0; ni < 4; ni++) {
                    const int np = ni >> 1, h = ni & 1;
                    MMA16816(acc[mi][ni], fa[mi], fb[np][h], fb[np][2 + h]);
                }
        }
        pAg += KS; pBg += KS;
    };

#pragma unroll 1
    for (int it2 = 0; it2 < K_ITERS; it2 += 2) {
        body(rA0, rB0, wA1, wB1, true);                    // read st0, load st1
        body(rA1, rB1, wA0, wB0, it2 + 2 < K_ITERS);       // read st1, load st0
    }

    // Epilogue: direct fp32 stores (coalesced float2 per thread)
#pragma unroll
    for (int mi = 0; mi < 4; mi++) {
        int row = m0 + warpM + mi * 16 + (lid >> 2);
#pragma unroll
        for (int ni = 0; ni < 4; ni++) {
            int col = n0 + warpN + ni * 8 + (lid & 3) * 2;
            float2 v0 = make_float2(acc[mi][ni][0], acc[mi][ni][1]);
            float2 v1 = make_float2(acc[mi][ni][2], acc[mi][ni][3]);
            *reinterpret_cast<float2*>(C + (size_t)row * NN + col)       = v0;
            *reinterpret_cast<float2*>(C + (size_t)(row + 8) * NN + col) = v1;
        }
    }
}

// ---------------------------------------------------------------------------
// Host launch
// ---------------------------------------------------------------------------
extern "C" void kernel_launch(void* const* d_in, const int* in_sizes, int n_in,
                              void* d_out, int out_size) {
    const float* A  = (const float*)d_in[0];
    const int*   Bp = (const int*)d_in[1];
    const float* sc = (const float*)d_in[2];
    float* C = (float*)d_out;

    void* pAh = nullptr; void* pWh = nullptr;
    cudaGetSymbolAddress(&pAh, g_Ah);
    cudaGetSymbolAddress(&pWh, g_Wh);

    prep_kernel<<<A_BLOCKS + W_BLOCKS, 512>>>(A, (__half*)pAh, Bp, sc, (__half*)pWh);

    cudaFuncSetAttribute(gemm_kernel, cudaFuncAttributeMaxDynamicSharedMemorySize,
                         SMEM_BYTES);
    gemm_kernel<<<(MM / TM) * (NN / TN), 512, SMEM_BYTES>>>(
        (const __half*)pAh, (const __half*)pWh, C);
}

// round 16
// speedup vs baseline: 1.0156x; 1.0156x over previous
#include <cuda_runtime.h>
#include <cuda_fp16.h>
#include <cstdint>

// Problem constants
#define MM 8192
#define NN 8192
#define KK 4096
#define TM 128
#define TN 256
#define KS 128              // K elems per pipeline stage (256B rows)
#define STAGES 2
#define K_ITERS (KK / KS)   // 32 (even)
#define GRID ((MM / TM) * (NN / TN) / 2)   // 1024: 2 tiles per CTA

// Static scratch (allocation-free rule: __device__ globals): 64 MB + 64 MB
__device__ __half g_Ah[(size_t)MM * KK];
__device__ __half g_Wh[(size_t)NN * KK];

// ---------------------------------------------------------------------------
// Fused prep kernel (512 threads).
// ---------------------------------------------------------------------------
#define A_BLOCKS (MM * KK / 8 / 512)             // 8192
#define W_BLOCKS ((NN / 512) * ((KK / 8) / 8))   // 1024

__global__ void prep_kernel(const float* __restrict__ A, __half* __restrict__ Ah,
                            const int* __restrict__ Bp, const float* __restrict__ s,
                            __half* __restrict__ Wh) {
    int b = blockIdx.x;
    if (b < A_BLOCKS) {
        size_t base = ((size_t)b * 512 + threadIdx.x) * 8;
        float4 v0 = *reinterpret_cast<const float4*>(A + base);
        float4 v1 = *reinterpret_cast<const float4*>(A + base + 4);
        union { __half h[8]; uint4 u; } out;
        out.h[0] = __float2half(v0.x); out.h[1] = __float2half(v0.y);
        out.h[2] = __float2half(v0.z); out.h[3] = __float2half(v0.w);
        out.h[4] = __float2half(v1.x); out.h[5] = __float2half(v1.y);
        out.h[6] = __float2half(v1.z); out.h[7] = __float2half(v1.w);
        *reinterpret_cast<uint4*>(Ah + base) = out.u;
    } else {
        int bw  = b - A_BLOCKS;
        int n   = (bw & 15) * 512 + threadIdx.x;      // 16 x-blocks
        int kp0 = (bw >> 4) * 8;                      // 8 packed rows = 64 k
        float sv = s[(size_t)(kp0 >> 4) * NN + n];    // group = kp/16
        __half* dst = Wh + (size_t)n * KK + kp0 * 8;
#pragma unroll
        for (int r = 0; r < 8; r++) {
            int packed = Bp[(size_t)(kp0 + r) * NN + n];
            union { __half h[8]; uint4 u; } out;
#pragma unroll
            for (int j = 0; j < 8; j++) {
                int q = (packed >> (4 * j)) & 0xF;
                out.h[j] = __float2half((float)(q - 8) * sv);
            }
            *reinterpret_cast<uint4*>(dst + r * 8) = out.u;
        }
    }
}

// ---------------------------------------------------------------------------
// GEMM: C[M,N] = Ah @ Wh^T (fp16 in, f32 acc)
// CTA 128x256, 512 threads, 16 warps (2m x 8n), warp tile 64x32.
// 2-stage cp.async pipeline, KS=128; outer loop unrolled x2 (hard parity).
// Persistent 2-tile CTA: tile 1 (m0+4096, same n0) stage-0 load is issued in
// tile 0's final pipeline slot and drains under tile 0's epilogue.
// ---------------------------------------------------------------------------
#define A_STAGE_BYTES 32768              // 128 x 128 x 2
#define B_STAGE_BYTES 65536              // 256 x 128 x 2
#define B_REGION (STAGES * A_STAGE_BYTES)                       // 65536
#define SMEM_BYTES (STAGES * (A_STAGE_BYTES + B_STAGE_BYTES))   // 196608
#define ROWSTEP (32 * KK)                // halves: 32 rows of gmem
#define SROWSTEP 8192                    // bytes: 32 rows of smem stage

__device__ __forceinline__ uint32_t smem_u32(const void* p) {
    uint32_t a;
    asm("{ .reg .u64 t; cvta.to.shared.u64 t, %1; cvt.u32.u64 %0, t; }" : "=r"(a) : "l"(p));
    return a;
}

#define CP_ASYNC16(smem, gmem) \
    asm volatile("cp.async.cg.shared.global [%0], [%1], 16;" :: "r"(smem), "l"(gmem))
#define CP_COMMIT() asm volatile("cp.async.commit_group;" ::: "memory")
#define CP_WAIT0()  asm volatile("cp.async.wait_group 0;" ::: "memory")

#define LDSM_X4(r, addr) \
    asm volatile("ldmatrix.sync.aligned.m8n8.x4.shared.b16 {%0,%1,%2,%3}, [%4];" \
        : "=r"((r)[0]), "=r"((r)[1]), "=r"((r)[2]), "=r"((r)[3]) : "r"(addr))

#define MMA16816(d, a, b0, b1) \
    asm volatile("mma.sync.aligned.m16n8k16.row.col.f32.f16.f16.f32 " \
        "{%0,%1,%2,%3}, {%4,%5,%6,%7}, {%8,%9}, {%0,%1,%2,%3};" \
        : "+f"((d)[0]), "+f"((d)[1]), "+f"((d)[2]), "+f"((d)[3]) \
        : "r"((a)[0]), "r"((a)[1]), "r"((a)[2]), "r"((a)[3]), "r"(b0), "r"(b1))

__global__ __launch_bounds__(512, 1) void gemm_kernel(
    const __half* __restrict__ gA,
    const __half* __restrict__ gB,
    float* __restrict__ C)
{
    extern __shared__ char smem[];
    const uint32_t sbase = smem_u32(smem);
    const int tid = threadIdx.x, wid = tid >> 5, lid = tid & 31;

    // CTA swizzle on tile 0: 8-wide m-bands sweeping n (L2 reuse).
    // Tile 1 = tile index + GRID => band+4 => m0+4096, same n0.
    const int TILES_N = NN / TN;        // 32
    int bid  = blockIdx.x;
    int band = bid / (8 * TILES_N);
    int rem  = bid % (8 * TILES_N);
    const int m0 = (band * 8 + (rem % 8)) * TM;
    const int n0 = (rem / 8) * TN;

    const int warpM = (wid & 1) * 64;   // 2 m-warps
    const int warpN = (wid >> 1) * 32;  // 8 n-warps

    // cp.async mapping: base row = tid>>4 (0..31), chunk c = tid&15.
    const int vb = tid >> 4, cchk = tid & 15;
    const uint32_t soffBase = (uint32_t)vb * 256 + (uint32_t)((cchk ^ (vb & 7)) << 4);
    const __half* pAg = gA + (size_t)(m0 + vb) * KK + cchk * 8;
    const __half* pBg = gB + (size_t)(n0 + vb) * KK + cchk * 8;

    // Hoisted cp.async destination bases (per parity)
    const uint32_t wA0 = sbase + soffBase;
    const uint32_t wA1 = wA0 + A_STAGE_BYTES;
    const uint32_t wB0 = sbase + B_REGION + soffBase;
    const uint32_t wB1 = wB0 + B_STAGE_BYTES;

    // Prologue: fill stage 0 for tile 0
    {
#pragma unroll
        for (int r = 0; r < 4; r++) CP_ASYNC16(wA0 + r * SROWSTEP, pAg + (size_t)r * ROWSTEP);
#pragma unroll
        for (int r = 0; r < 8; r++) CP_ASYNC16(wB0 + r * SROWSTEP, pBg + (size_t)r * ROWSTEP);
        CP_COMMIT();
        pAg += KS; pBg += KS;
    }

    float acc[4][4][4];
#pragma unroll
    for (int mi = 0; mi < 4; mi++)
#pragma unroll
        for (int ni = 0; ni < 4; ni++)
#pragma unroll
            for (int v = 0; v < 4; v++) acc[mi][ni][v] = 0.f;

    const int lrow  = lid & 15;          // row within 16-row subtile
    const int lhalf = lid >> 4;          // k-chunk half (0/1)
    const int lsw   = lrow & 7;          // swizzle key

    // Hoisted LDSM read bases (per parity)
    const uint32_t rA0 = sbase + (uint32_t)(warpM + lrow) * 256;
    const uint32_t rA1 = rA0 + A_STAGE_BYTES;
    const uint32_t rB0 = sbase + B_REGION + (uint32_t)(warpN + lrow) * 256;
    const uint32_t rB1 = rB0 + B_STAGE_BYTES;

    // One stage body: read (aR,bR), load next stage into (lA,lB).
    auto body = [&](uint32_t aR, uint32_t bR, uint32_t lA, uint32_t lB, bool doLoad) {
        CP_WAIT0();
        __syncthreads();
#pragma unroll
        for (int kt = 0; kt < 8; kt++) {
            const uint32_t off = (uint32_t)(((kt * 2 + lhalf) ^ lsw) << 4);
            const uint32_t aAdr = aR + off;
            const uint32_t bAdr = bR + off;
            uint32_t fa[4][4], fb[2][4];
            LDSM_X4(fa[0], aAdr);
            LDSM_X4(fb[0], bAdr);
            LDSM_X4(fb[1], bAdr + 4096);
            LDSM_X4(fa[1], aAdr + 4096);
            LDSM_X4(fa[2], aAdr + 8192);
            LDSM_X4(fa[3], aAdr + 12288);
            // Next stage's cp.asyncs: 2 per slot, kt0..5
            if (doLoad && kt < 6) {
                if (kt < 4) {
                    CP_ASYNC16(lA + kt * SROWSTEP, pAg + (size_t)kt * ROWSTEP);
                    CP_ASYNC16(lB + kt * SROWSTEP, pBg + (size_t)kt * ROWSTEP);
                } else {
                    CP_ASYNC16(lB + (2 * kt - 4) * SROWSTEP, pBg + (size_t)(2 * kt - 4) * ROWSTEP);
                    CP_ASYNC16(lB + (2 * kt - 3) * SROWSTEP, pBg + (size_t)(2 * kt - 3) * ROWSTEP);
                }
            }
            if (kt == 5) { CP_COMMIT(); }
#pragma unroll
            for (int mi = 0; mi < 4; mi++)
#pragma unroll
                for (int ni = 0; ni < 4; ni++) {
                    const int np = ni >> 1, h = ni & 1;
                    MMA16816(acc[mi][ni], fa[mi], fb[np][h], fb[np][2 + h]);
                }
        }
        pAg += KS; pBg += KS;
    };

    // Mainloop for one tile. In the final pipeline slot, either load the next
    // tile's stage 0 (switchNext) or idle (last tile).
    auto mainloop = [&](bool switchNext) {
#pragma unroll 1
        for (int it2 = 0; it2 < K_ITERS; it2 += 2) {
            body(rA0, rB0, wA1, wB1, true);                  // read st0, load st1
            const bool lastPair = (it2 + 2 >= K_ITERS);
            if (lastPair && switchNext) {
                // Reset pointers to tile 1 (m0+4096, same n0, k=0)
                pAg = gA + (size_t)(m0 + 4096 + vb) * KK + cchk * 8;
                pBg = gB + (size_t)(n0 + vb) * KK + cchk * 8;
            }
            body(rA1, rB1, wA0, wB0, !lastPair || switchNext);  // read st1, load st0
        }
    };

    auto epilogue = [&](int m0e) {
#pragma unroll
        for (int mi = 0; mi < 4; mi++) {
            int row = m0e + warpM + mi * 16 + (lid >> 2);
#pragma unroll
            for (int ni = 0; ni < 4; ni++) {
                int col = n0 + warpN + ni * 8 + (lid & 3) * 2;
                float2 v0 = make_float2(acc[mi][ni][0], acc[mi][ni][1]);
                float2 v1 = make_float2(acc[mi][ni][2], acc[mi][ni][3]);
                *reinterpret_cast<float2*>(C + (size_t)row * NN + col)       = v0;
                *reinterpret_cast<float2*>(C + (size_t)(row + 8) * NN + col) = v1;
            }
        }
    };

    // Tile 0
    mainloop(true);
    epilogue(m0);

    // Reset accumulators for tile 1 (its stage-0 load is already in flight)
#pragma unroll
    for (int mi = 0; mi < 4; mi++)
#pragma unroll
        for (int ni = 0; ni < 4; ni++)
#pragma unroll
            for (int v = 0; v < 4; v++) acc[mi][ni][v] = 0.f;

    // Tile 1 (pAg/pBg already advanced to k=1 by the switch body)
    mainloop(false);
    epilogue(m0 + 4096);
}

// ---------------------------------------------------------------------------
// Host launch
// ---------------------------------------------------------------------------
extern "C" void kernel_launch(void* const* d_in, const int* in_sizes, int n_in,
                              void* d_out, int out_size) {
    const float* A  = (const float*)d_in[0];
    const int*   Bp = (const int*)d_in[1];
    const float* sc = (const float*)d_in[2];
    float* C = (float*)d_out;

    void* pAh = nullptr; void* pWh = nullptr;
    cudaGetSymbolAddress(&pAh, g_Ah);
    cudaGetSymbolAddress(&pWh, g_Wh);

    prep_kernel<<<A_BLOCKS + W_BLOCKS, 512>>>(A, (__half*)pAh, Bp, sc, (__half*)pWh);

    cudaFuncSetAttribute(gemm_kernel, cudaFuncAttributeMaxDynamicSharedMemorySize,
                         SMEM_BYTES);
    gemm_kernel<<<GRID, 512, SMEM_BYTES>>>(
        (const __half*)pAh, (const __half*)pWh, C);
}